// round 1
// baseline (speedup 1.0000x reference)
#include <cuda_runtime.h>

#define N_ROWS  262144
#define IN_DIM  512
#define OUT_DIM 128

#define XSUM_BLOCKS 32768   // 8 rows per block (one warp per row)
#define CMP_BLOCKS  512     // 512 threads each -> 262144 elements

// ---- device scratch (no allocations allowed) ----
__device__ float  g_wsum[IN_DIM];
__device__ double g_sumb;
__device__ double g_partials[XSUM_BLOCKS];
__device__ float  g_thr;
__device__ int    g_cnt[CMP_BLOCKS];
__device__ int    g_off[CMP_BLOCKS];
__device__ int    g_total;

// ============================================================
// 1. wsum[k] = sum_o W[o,k] (fp64), sumb = sum(b) (fp64)
// ============================================================
__global__ void wsum_kernel(const float* __restrict__ W, const float* __restrict__ b) {
    int k = threadIdx.x;  // 512 threads
    double s = 0.0;
    #pragma unroll 8
    for (int o = 0; o < OUT_DIM; o++)
        s += (double)W[o * IN_DIM + k];
    g_wsum[k] = (float)s;
    if (k == 0) {
        double sb = 0.0;
        for (int o = 0; o < OUT_DIM; o++) sb += (double)b[o];
        g_sumb = sb;
    }
}

// ============================================================
// 2. per-block partial of S = sum_n x_n . wsum (warp per row)
// ============================================================
__global__ __launch_bounds__(256) void xsum_kernel(const float* __restrict__ x) {
    __shared__ float sw[IN_DIM];
    for (int i = threadIdx.x; i < IN_DIM; i += 256) sw[i] = g_wsum[i];
    __syncthreads();

    int warp = threadIdx.x >> 5;
    int lane = threadIdx.x & 31;
    size_t row = (size_t)blockIdx.x * 8 + warp;
    const float* xr = x + row * IN_DIM;

    float acc = 0.0f;
    #pragma unroll
    for (int j = 0; j < 16; j++) {
        int c = lane + 32 * j;
        acc += xr[c] * sw[c];
    }
    #pragma unroll
    for (int s = 16; s; s >>= 1)
        acc += __shfl_xor_sync(0xFFFFFFFFu, acc, s);

    __shared__ double wsums[8];
    if (lane == 0) wsums[warp] = (double)acc;
    __syncthreads();
    if (threadIdx.x == 0) {
        double s = 0.0;
        #pragma unroll
        for (int w = 0; w < 8; w++) s += wsums[w];
        g_partials[blockIdx.x] = s;
    }
}

// ============================================================
// 3. deterministic reduction of partials -> threshold (float)
// ============================================================
__global__ void thr_kernel() {
    __shared__ double sm[512];
    double s = 0.0;
    for (int i = threadIdx.x; i < XSUM_BLOCKS; i += 512)
        s += g_partials[i];
    sm[threadIdx.x] = s;
    __syncthreads();
    for (int st = 256; st; st >>= 1) {
        if (threadIdx.x < st) sm[threadIdx.x] += sm[threadIdx.x + st];
        __syncthreads();
    }
    if (threadIdx.x == 0)
        g_thr = (float)(sm[0] / (double)N_ROWS + g_sumb);
}

// ============================================================
// 4. GEMM: out[n,o] = x[n,:] . W[o,:] + b[o]
//    128x128 tile, K-step 16, 256 threads, 8x8 per thread
// ============================================================
__global__ __launch_bounds__(256, 2) void gemm_kernel(
    const float* __restrict__ x, const float* __restrict__ W,
    const float* __restrict__ b, float* __restrict__ out)
{
    __shared__ float xs[16][128];
    __shared__ float ws[16][128];

    const int tid = threadIdx.x;
    const int tx = tid & 15;   // n group
    const int ty = tid >> 4;   // m group
    const size_t m0 = (size_t)blockIdx.x * 128;
    const float* xb = x + m0 * IN_DIM;

    float acc[8][8];
    #pragma unroll
    for (int i = 0; i < 8; i++)
        #pragma unroll
        for (int j = 0; j < 8; j++) acc[i][j] = 0.0f;

    for (int k0 = 0; k0 < IN_DIM; k0 += 16) {
        // cooperative load: 128 rows x 16 k, float4 per transfer, store transposed
        #pragma unroll
        for (int t = 0; t < 2; t++) {
            int idx = tid * 2 + t;      // 0..511
            int row = idx >> 2;         // 0..127
            int c4  = idx & 3;          // 0..3
            float4 v = *(const float4*)(xb + (size_t)row * IN_DIM + k0 + c4 * 4);
            xs[c4 * 4 + 0][row] = v.x;
            xs[c4 * 4 + 1][row] = v.y;
            xs[c4 * 4 + 2][row] = v.z;
            xs[c4 * 4 + 3][row] = v.w;
            float4 w = *(const float4*)(W + (size_t)row * IN_DIM + k0 + c4 * 4);
            ws[c4 * 4 + 0][row] = w.x;
            ws[c4 * 4 + 1][row] = w.y;
            ws[c4 * 4 + 2][row] = w.z;
            ws[c4 * 4 + 3][row] = w.w;
        }
        __syncthreads();

        #pragma unroll
        for (int kk = 0; kk < 16; kk++) {
            float4 a0 = *(const float4*)&xs[kk][ty * 8];
            float4 a1 = *(const float4*)&xs[kk][ty * 8 + 4];
            float4 b0 = *(const float4*)&ws[kk][tx * 8];
            float4 b1 = *(const float4*)&ws[kk][tx * 8 + 4];
            float av[8] = {a0.x, a0.y, a0.z, a0.w, a1.x, a1.y, a1.z, a1.w};
            float bv[8] = {b0.x, b0.y, b0.z, b0.w, b1.x, b1.y, b1.z, b1.w};
            #pragma unroll
            for (int i = 0; i < 8; i++)
                #pragma unroll
                for (int j = 0; j < 8; j++)
                    acc[i][j] += av[i] * bv[j];
        }
        __syncthreads();
    }

    // bias + store
    float bv[8];
    #pragma unroll
    for (int j = 0; j < 8; j++) bv[j] = b[tx * 8 + j];

    #pragma unroll
    for (int i = 0; i < 8; i++) {
        size_t m = m0 + ty * 8 + i;
        float4 o0, o1;
        o0.x = acc[i][0] + bv[0]; o0.y = acc[i][1] + bv[1];
        o0.z = acc[i][2] + bv[2]; o0.w = acc[i][3] + bv[3];
        o1.x = acc[i][4] + bv[4]; o1.y = acc[i][5] + bv[5];
        o1.z = acc[i][6] + bv[6]; o1.w = acc[i][7] + bv[7];
        *(float4*)(out + m * OUT_DIM + tx * 8)     = o0;
        *(float4*)(out + m * OUT_DIM + tx * 8 + 4) = o1;
    }
}

// ============================================================
// 5-8. ordered stream compaction of (mask > thr)
// ============================================================
__global__ void count_kernel(const float* __restrict__ mask) {
    int i = blockIdx.x * 512 + threadIdx.x;
    int p = mask[i] > g_thr;
    unsigned bal = __ballot_sync(0xFFFFFFFFu, p);
    __shared__ int wc[16];
    if ((threadIdx.x & 31) == 0) wc[threadIdx.x >> 5] = __popc(bal);
    __syncthreads();
    if (threadIdx.x == 0) {
        int s = 0;
        #pragma unroll
        for (int w = 0; w < 16; w++) s += wc[w];
        g_cnt[blockIdx.x] = s;
    }
}

__global__ void scan_kernel() {  // 1 block, 512 threads
    __shared__ int sm[512];
    int v = g_cnt[threadIdx.x];
    sm[threadIdx.x] = v;
    __syncthreads();
    for (int st = 1; st < 512; st <<= 1) {
        int t = (threadIdx.x >= st) ? sm[threadIdx.x - st] : 0;
        __syncthreads();
        sm[threadIdx.x] += t;
        __syncthreads();
    }
    g_off[threadIdx.x] = sm[threadIdx.x] - v;  // exclusive
    if (threadIdx.x == 511) g_total = sm[511];
}

__global__ void scatter_kernel(const float* __restrict__ mask, float* __restrict__ idx_out) {
    int i = blockIdx.x * 512 + threadIdx.x;
    int lane = threadIdx.x & 31;
    int w = threadIdx.x >> 5;
    int p = mask[i] > g_thr;
    unsigned bal = __ballot_sync(0xFFFFFFFFu, p);
    __shared__ int woff[16];
    if (lane == 0) woff[w] = __popc(bal);
    __syncthreads();
    if (threadIdx.x == 0) {
        int s = g_off[blockIdx.x];
        #pragma unroll
        for (int ww = 0; ww < 16; ww++) { int c = woff[ww]; woff[ww] = s; s += c; }
    }
    __syncthreads();
    if (p) {
        int pos = woff[w] + __popc(bal & ((1u << lane) - 1u));
        idx_out[pos] = (float)i;
    }
}

__global__ void fill_kernel(float* __restrict__ idx_out) {
    int i = blockIdx.x * 512 + threadIdx.x;
    if (i >= g_total) idx_out[i] = -1.0f;
}

// ============================================================
// launch
// ============================================================
extern "C" void kernel_launch(void* const* d_in, const int* in_sizes, int n_in,
                              void* d_out, int out_size) {
    const float* x    = (const float*)d_in[0];
    const float* mask = (const float*)d_in[1];
    const float* W    = (const float*)d_in[2];
    const float* b    = (const float*)d_in[3];
    float* out = (float*)d_out;
    float* idx_out = out + (size_t)N_ROWS * OUT_DIM;

    wsum_kernel<<<1, 512>>>(W, b);
    xsum_kernel<<<XSUM_BLOCKS, 256>>>(x);
    thr_kernel<<<1, 512>>>();
    gemm_kernel<<<N_ROWS / 128, 256>>>(x, W, b, out);
    count_kernel<<<CMP_BLOCKS, 512>>>(mask);
    scan_kernel<<<1, 512>>>();
    scatter_kernel<<<CMP_BLOCKS, 512>>>(mask, idx_out);
    fill_kernel<<<CMP_BLOCKS, 512>>>(idx_out);
}

// round 3
// speedup vs baseline: 2.1181x; 2.1181x over previous
#include <cuda_runtime.h>
#include <cuda_bf16.h>
#include <cstdint>

#define N_ROWS  262144
#define IN_DIM  512
#define OUT_DIM 128
#define GEMM_BLOCKS (N_ROWS / 128)   // 2048
#define CMP_BLOCKS  512

// ---------------- device scratch (no allocations allowed) ----------------
__device__ __align__(16) __nv_bfloat16 g_Whi[OUT_DIM * IN_DIM];
__device__ __align__(16) __nv_bfloat16 g_Wlo[OUT_DIM * IN_DIM];
__device__ double g_partials[GEMM_BLOCKS];
__device__ float  g_thr;
__device__ int    g_cnt[CMP_BLOCKS];
__device__ int    g_off[CMP_BLOCKS];
__device__ int    g_total;

// ---------------- smem layout (dynamic) ----------------
// two stages, each: AH 16K | AL 16K | BH 16K | BL 16K  (128 rows x 128B, SW128)
#define SM_AH(s) ((s) * 65536 + 0)
#define SM_AL(s) ((s) * 65536 + 16384)
#define SM_BH(s) ((s) * 65536 + 32768)
#define SM_BL(s) ((s) * 65536 + 49152)
#define SM_BIAS  131072
#define SM_RED   (131072 + 512)
#define SMEM_TOTAL (131072 + 512 + 64)

#define SWZ(o) ((o) ^ (((o) >> 3) & 0x70))

__device__ __forceinline__ uint32_t smem_u32(const void* p) {
    uint32_t a;
    asm("{ .reg .u64 t; cvta.to.shared.u64 t, %1; cvt.u32.u64 %0, t; }" : "=r"(a) : "l"(p));
    return a;
}

__device__ __forceinline__ void ldsm4(uint32_t* r, uint32_t addr) {
    asm volatile("ldmatrix.sync.aligned.m8n8.x4.shared.b16 {%0,%1,%2,%3}, [%4];"
        : "=r"(r[0]), "=r"(r[1]), "=r"(r[2]), "=r"(r[3]) : "r"(addr));
}

__device__ __forceinline__ void mma16816(float* d, const uint32_t* a, uint32_t b0, uint32_t b1) {
    asm volatile("mma.sync.aligned.m16n8k16.row.col.f32.bf16.bf16.f32 "
        "{%0,%1,%2,%3},{%4,%5,%6,%7},{%8,%9},{%0,%1,%2,%3};"
        : "+f"(d[0]), "+f"(d[1]), "+f"(d[2]), "+f"(d[3])
        : "r"(a[0]), "r"(a[1]), "r"(a[2]), "r"(a[3]), "r"(b0), "r"(b1));
}

#define CP_ASYNC16(dst, src) \
    asm volatile("cp.async.cg.shared.global [%0], [%1], 16;" :: "r"(dst), "l"(src) : "memory")
#define CP_COMMIT()  asm volatile("cp.async.commit_group;" ::: "memory")
#define CP_WAIT0()   asm volatile("cp.async.wait_group 0;" ::: "memory")

// ============================================================
// 0. split W into bf16 hi/lo
// ============================================================
__global__ void wsplit_kernel(const float* __restrict__ W) {
    int i = blockIdx.x * 256 + threadIdx.x;   // grid 256 -> 65536
    float w = W[i];
    __nv_bfloat16 h = __float2bfloat16(w);
    g_Whi[i] = h;
    g_Wlo[i] = __float2bfloat16(w - __bfloat162float(h));
}

// ============================================================
// helpers for the GEMM pipeline
// ============================================================
__device__ __forceinline__ void load_W_chunk(uint32_t sb, int s, int k0, int tid) {
    #pragma unroll
    for (int i = 0; i < 4; i++) {
        int l = tid + 256 * i;          // 0..1023
        int row = l >> 3, u = l & 7;
        uint32_t off = SWZ((uint32_t)(row * 128 + u * 16));
        const void* srcH = g_Whi + row * IN_DIM + k0 + u * 8;
        const void* srcL = g_Wlo + row * IN_DIM + k0 + u * 8;
        CP_ASYNC16(sb + SM_BH(s) + off, srcH);
        CP_ASYNC16(sb + SM_BL(s) + off, srcL);
    }
    CP_COMMIT();
}

__device__ __forceinline__ void ldg_x(const float* xb, int k0, int tid, float4* xv) {
    #pragma unroll
    for (int i = 0; i < 8; i++) {
        int l = tid + 256 * i;          // 0..2047
        int row = l >> 4, c4 = l & 15;
        xv[i] = __ldg((const float4*)(xb + (size_t)row * IN_DIM + k0 + c4 * 4));
    }
}

__device__ __forceinline__ void sts_x(char* smem, int s, int tid, const float4* xv) {
    #pragma unroll
    for (int i = 0; i < 8; i++) {
        int l = tid + 256 * i;
        int row = l >> 4, c4 = l & 15;
        float4 v = xv[i];
        __nv_bfloat162 h01 = __floats2bfloat162_rn(v.x, v.y);
        __nv_bfloat162 h23 = __floats2bfloat162_rn(v.z, v.w);
        float2 hf01 = __bfloat1622float2(h01);
        float2 hf23 = __bfloat1622float2(h23);
        __nv_bfloat162 l01 = __floats2bfloat162_rn(v.x - hf01.x, v.y - hf01.y);
        __nv_bfloat162 l23 = __floats2bfloat162_rn(v.z - hf23.x, v.w - hf23.y);
        uint32_t off = SWZ((uint32_t)(row * 128 + c4 * 8));
        uint2 hv = make_uint2(*(uint32_t*)&h01, *(uint32_t*)&h23);
        uint2 lv = make_uint2(*(uint32_t*)&l01, *(uint32_t*)&l23);
        *(uint2*)(smem + SM_AH(s) + off) = hv;
        *(uint2*)(smem + SM_AL(s) + off) = lv;
    }
}

// ============================================================
// 1. HMMA GEMM (bf16 3-product split) + fused row-sum partial
// ============================================================
__global__ void __launch_bounds__(256, 1) gemm_tc_kernel(
    const float* __restrict__ x, const float* __restrict__ bias, float* __restrict__ out)
{
    extern __shared__ char smem[];
    const uint32_t sb = smem_u32(smem);
    const int tid = threadIdx.x, wid = tid >> 5, lane = tid & 31;
    const int wm = wid & 3, wn = wid >> 2;       // warp tile: 32(M) x 64(N)
    const size_t m0 = (size_t)blockIdx.x * 128;
    const float* xb = x + m0 * IN_DIM;

    if (tid < 128) ((float*)(smem + SM_BIAS))[tid] = bias[tid];

    float acc[2][8][4];
    #pragma unroll
    for (int mt = 0; mt < 2; mt++)
        #pragma unroll
        for (int nt = 0; nt < 8; nt++)
            #pragma unroll
            for (int j = 0; j < 4; j++) acc[mt][nt][j] = 0.0f;

    // ---- prologue: chunk 0 ----
    load_W_chunk(sb, 0, 0, tid);
    float4 xv[8];
    ldg_x(xb, 0, tid, xv);
    CP_WAIT0();
    sts_x(smem, 0, tid, xv);
    __syncthreads();

    const int arow  = lane & 15;
    const int acolb = ((lane >> 4) & 1) * 16;
    const int brow  = (lane & 7) + ((lane >> 4) & 1) * 8;
    const int bcolb = ((lane >> 3) & 1) * 16;

    for (int c = 0; c < 8; c++) {
        const int s = c & 1, ns = s ^ 1;
        if (c < 7) {
            load_W_chunk(sb, ns, (c + 1) * 64, tid);
            ldg_x(xb, (c + 1) * 64, tid, xv);
        }
        const uint32_t sAH = sb + SM_AH(s), sAL = sb + SM_AL(s);
        const uint32_t sBH = sb + SM_BH(s), sBL = sb + SM_BL(s);

        #pragma unroll
        for (int kk = 0; kk < 4; kk++) {
            uint32_t ah[2][4], al[2][4], bh[4][4], bl[4][4];
            #pragma unroll
            for (int mt = 0; mt < 2; mt++) {
                uint32_t off = SWZ((uint32_t)((32 * wm + 16 * mt + arow) * 128 + kk * 32 + acolb));
                ldsm4(ah[mt], sAH + off);
                ldsm4(al[mt], sAL + off);
            }
            #pragma unroll
            for (int np = 0; np < 4; np++) {
                uint32_t off = SWZ((uint32_t)((64 * wn + 16 * np + brow) * 128 + kk * 32 + bcolb));
                ldsm4(bh[np], sBH + off);
                ldsm4(bl[np], sBL + off);
            }
            #pragma unroll
            for (int mt = 0; mt < 2; mt++)
                #pragma unroll
                for (int nt = 0; nt < 8; nt++) {
                    const uint32_t* ph = &bh[nt >> 1][(nt & 1) * 2];
                    const uint32_t* pl = &bl[nt >> 1][(nt & 1) * 2];
                    mma16816(acc[mt][nt], ah[mt], ph[0], ph[1]);   // xh*Wh
                    mma16816(acc[mt][nt], ah[mt], pl[0], pl[1]);   // xh*Wl
                    mma16816(acc[mt][nt], al[mt], ph[0], ph[1]);   // xl*Wh
                }
        }
        if (c < 7) {
            CP_WAIT0();
            sts_x(smem, ns, tid, xv);
        }
        __syncthreads();
    }

    // ---- epilogue: bias + store + fp64 partial of sum(out_tile) ----
    const float* bs = (const float*)(smem + SM_BIAS);
    double dsum = 0.0;
    #pragma unroll
    for (int mt = 0; mt < 2; mt++) {
        const size_t r0 = m0 + 32 * wm + 16 * mt + (lane >> 2);
        #pragma unroll
        for (int nt = 0; nt < 8; nt++) {
            int col = 64 * wn + 8 * nt + 2 * (lane & 3);
            float b0 = bs[col], b1 = bs[col + 1];
            float2 v0 = make_float2(acc[mt][nt][0] + b0, acc[mt][nt][1] + b1);
            float2 v1 = make_float2(acc[mt][nt][2] + b0, acc[mt][nt][3] + b1);
            *(float2*)(out + r0 * OUT_DIM + col)       = v0;
            *(float2*)(out + (r0 + 8) * OUT_DIM + col) = v1;
            dsum += (double)acc[mt][nt][0] + (double)acc[mt][nt][1]
                  + (double)acc[mt][nt][2] + (double)acc[mt][nt][3];
        }
    }
    #pragma unroll
    for (int st = 16; st; st >>= 1)
        dsum += __shfl_xor_sync(0xFFFFFFFFu, dsum, st);
    double* red = (double*)(smem + SM_RED);
    if (lane == 0) red[wid] = dsum;
    __syncthreads();
    if (tid == 0) {
        double t = 0.0;
        #pragma unroll
        for (int w = 0; w < 8; w++) t += red[w];
        g_partials[blockIdx.x] = t;
    }
}

// ============================================================
// 2. threshold = sum(partials)/N + sum(b)
// ============================================================
__global__ void thr_kernel(const float* __restrict__ bias) {
    __shared__ double sm[512];
    double s = 0.0;
    for (int i = threadIdx.x; i < GEMM_BLOCKS; i += 512)
        s += g_partials[i];
    sm[threadIdx.x] = s;
    __syncthreads();
    for (int st = 256; st; st >>= 1) {
        if (threadIdx.x < st) sm[threadIdx.x] += sm[threadIdx.x + st];
        __syncthreads();
    }
    if (threadIdx.x == 0) {
        double sb2 = 0.0;
        for (int o = 0; o < OUT_DIM; o++) sb2 += (double)bias[o];
        g_thr = (float)(sm[0] / (double)N_ROWS + sb2);
    }
}

// ============================================================
// 3-6. ordered stream compaction of (mask > thr)
// ============================================================
__global__ void count_kernel(const float* __restrict__ mask) {
    int i = blockIdx.x * 512 + threadIdx.x;
    int p = mask[i] > g_thr;
    unsigned bal = __ballot_sync(0xFFFFFFFFu, p);
    __shared__ int wc[16];
    if ((threadIdx.x & 31) == 0) wc[threadIdx.x >> 5] = __popc(bal);
    __syncthreads();
    if (threadIdx.x == 0) {
        int s = 0;
        #pragma unroll
        for (int w = 0; w < 16; w++) s += wc[w];
        g_cnt[blockIdx.x] = s;
    }
}

__global__ void scan_kernel() {
    __shared__ int sm[512];
    int v = g_cnt[threadIdx.x];
    sm[threadIdx.x] = v;
    __syncthreads();
    for (int st = 1; st < 512; st <<= 1) {
        int t = (threadIdx.x >= st) ? sm[threadIdx.x - st] : 0;
        __syncthreads();
        sm[threadIdx.x] += t;
        __syncthreads();
    }
    g_off[threadIdx.x] = sm[threadIdx.x] - v;
    if (threadIdx.x == 511) g_total = sm[511];
}

__global__ void scatter_kernel(const float* __restrict__ mask, float* __restrict__ idx_out) {
    int i = blockIdx.x * 512 + threadIdx.x;
    int lane = threadIdx.x & 31;
    int w = threadIdx.x >> 5;
    int p = mask[i] > g_thr;
    unsigned bal = __ballot_sync(0xFFFFFFFFu, p);
    __shared__ int woff[16];
    if (lane == 0) woff[w] = __popc(bal);
    __syncthreads();
    if (threadIdx.x == 0) {
        int s = g_off[blockIdx.x];
        #pragma unroll
        for (int ww = 0; ww < 16; ww++) { int c = woff[ww]; woff[ww] = s; s += c; }
    }
    __syncthreads();
    if (p) {
        int pos = woff[w] + __popc(bal & ((1u << lane) - 1u));
        idx_out[pos] = (float)i;
    }
}

__global__ void fill_kernel(float* __restrict__ idx_out) {
    int i = blockIdx.x * 512 + threadIdx.x;
    if (i >= g_total) idx_out[i] = -1.0f;
}

// ============================================================
// launch
// ============================================================
extern "C" void kernel_launch(void* const* d_in, const int* in_sizes, int n_in,
                              void* d_out, int out_size) {
    const float* x    = (const float*)d_in[0];
    const float* mask = (const float*)d_in[1];
    const float* W    = (const float*)d_in[2];
    const float* b    = (const float*)d_in[3];
    float* out = (float*)d_out;
    float* idx_out = out + (size_t)N_ROWS * OUT_DIM;

    cudaFuncSetAttribute(gemm_tc_kernel, cudaFuncAttributeMaxDynamicSharedMemorySize, SMEM_TOTAL);

    wsplit_kernel<<<256, 256>>>(W);
    gemm_tc_kernel<<<GEMM_BLOCKS, 256, SMEM_TOTAL>>>(x, b, out);
    thr_kernel<<<1, 512>>>(b);
    count_kernel<<<CMP_BLOCKS, 512>>>(mask);
    scan_kernel<<<1, 512>>>();
    scatter_kernel<<<CMP_BLOCKS, 512>>>(mask, idx_out);
    fill_kernel<<<CMP_BLOCKS, 512>>>(idx_out);
}

// round 4
// speedup vs baseline: 3.2401x; 1.5297x over previous
#include <cuda_runtime.h>
#include <cuda_fp16.h>
#include <cstdint>

#define N_ROWS  262144
#define IN_DIM  512
#define OUT_DIM 128
#define GEMM_BLOCKS (N_ROWS / 128)   // 2048
#define CMP_BLOCKS  512

// ---------------- device scratch (no allocations allowed) ----------------
__device__ __align__(16) __half g_Whi[OUT_DIM * IN_DIM];
__device__ __align__(16) __half g_Wlo[OUT_DIM * IN_DIM];
__device__ double g_partials[GEMM_BLOCKS];
__device__ float  g_thr;
__device__ int    g_cnt[CMP_BLOCKS];
__device__ int    g_off[CMP_BLOCKS];
__device__ int    g_total;

// ---------------- smem layout (dynamic) ----------------
// two stages, each: A 16K | BH 16K | BL 16K   (128 rows x 128B, SW128)
#define SM_A(s)  ((s) * 49152 + 0)
#define SM_BH(s) ((s) * 49152 + 16384)
#define SM_BL(s) ((s) * 49152 + 32768)
#define SM_BIAS  98304
#define SM_RED   (98304 + 512)
#define SMEM_TOTAL (98304 + 512 + 64)

#define SWZ(o) ((o) ^ (((o) >> 3) & 0x70))

__device__ __forceinline__ uint32_t smem_u32(const void* p) {
    uint32_t a;
    asm("{ .reg .u64 t; cvta.to.shared.u64 t, %1; cvt.u32.u64 %0, t; }" : "=r"(a) : "l"(p));
    return a;
}

__device__ __forceinline__ void ldsm4(uint32_t* r, uint32_t addr) {
    asm volatile("ldmatrix.sync.aligned.m8n8.x4.shared.b16 {%0,%1,%2,%3}, [%4];"
        : "=r"(r[0]), "=r"(r[1]), "=r"(r[2]), "=r"(r[3]) : "r"(addr));
}

__device__ __forceinline__ void mma16816(float* d, const uint32_t* a, uint32_t b0, uint32_t b1) {
    asm volatile("mma.sync.aligned.m16n8k16.row.col.f32.f16.f16.f32 "
        "{%0,%1,%2,%3},{%4,%5,%6,%7},{%8,%9},{%0,%1,%2,%3};"
        : "+f"(d[0]), "+f"(d[1]), "+f"(d[2]), "+f"(d[3])
        : "r"(a[0]), "r"(a[1]), "r"(a[2]), "r"(a[3]), "r"(b0), "r"(b1));
}

#define CP_ASYNC16(dst, src) \
    asm volatile("cp.async.cg.shared.global [%0], [%1], 16;" :: "r"(dst), "l"(src) : "memory")
#define CP_COMMIT()  asm volatile("cp.async.commit_group;" ::: "memory")
#define CP_WAIT0()   asm volatile("cp.async.wait_group 0;" ::: "memory")

// ============================================================
// 0. split W into fp16 hi/lo
// ============================================================
__global__ void wsplit_kernel(const float* __restrict__ W) {
    int i = blockIdx.x * 256 + threadIdx.x;   // grid 256 -> 65536
    float w = W[i];
    __half h = __float2half_rn(w);
    g_Whi[i] = h;
    g_Wlo[i] = __float2half_rn(w - __half2float(h));
}

// ============================================================
// GEMM pipeline helpers
// ============================================================
__device__ __forceinline__ void load_W_chunk(uint32_t sb, int s, int k0, int tid) {
    #pragma unroll
    for (int i = 0; i < 4; i++) {
        int l = tid + 256 * i;          // 0..1023
        int row = l >> 3, u = l & 7;
        uint32_t off = SWZ((uint32_t)(row * 128 + u * 16));
        CP_ASYNC16(sb + SM_BH(s) + off, g_Whi + row * IN_DIM + k0 + u * 8);
        CP_ASYNC16(sb + SM_BL(s) + off, g_Wlo + row * IN_DIM + k0 + u * 8);
    }
    CP_COMMIT();
}

__device__ __forceinline__ void ldg_cvt_x(const float* xb, int k0, int tid, uint2* xv) {
    #pragma unroll
    for (int i = 0; i < 8; i++) {
        int l = tid + 256 * i;          // 0..2047
        int row = l >> 4, c4 = l & 15;
        float4 v = __ldg((const float4*)(xb + (size_t)row * IN_DIM + k0 + c4 * 4));
        __half2 h01 = __floats2half2_rn(v.x, v.y);
        __half2 h23 = __floats2half2_rn(v.z, v.w);
        xv[i] = make_uint2(*(uint32_t*)&h01, *(uint32_t*)&h23);
    }
}

__device__ __forceinline__ void sts_x(char* smem, int s, int tid, const uint2* xv) {
    #pragma unroll
    for (int i = 0; i < 8; i++) {
        int l = tid + 256 * i;
        int row = l >> 4, c4 = l & 15;
        uint32_t off = SWZ((uint32_t)(row * 128 + c4 * 8));
        *(uint2*)(smem + SM_A(s) + off) = xv[i];
    }
}

// ============================================================
// 1. HMMA GEMM (fp16: xh*Wh + xh*Wl) + fused row-sum partial
// ============================================================
__global__ void __launch_bounds__(256, 2) gemm_tc_kernel(
    const float* __restrict__ x, const float* __restrict__ bias, float* __restrict__ out)
{
    extern __shared__ char smem[];
    const uint32_t sb = smem_u32(smem);
    const int tid = threadIdx.x, wid = tid >> 5, lane = tid & 31;
    const int wm = wid & 3, wn = wid >> 2;       // warp tile: 32(M) x 64(N)
    const size_t m0 = (size_t)blockIdx.x * 128;
    const float* xb = x + m0 * IN_DIM;

    if (tid < 128) ((float*)(smem + SM_BIAS))[tid] = bias[tid];

    float acc[2][8][4];
    #pragma unroll
    for (int mt = 0; mt < 2; mt++)
        #pragma unroll
        for (int nt = 0; nt < 8; nt++)
            #pragma unroll
            for (int j = 0; j < 4; j++) acc[mt][nt][j] = 0.0f;

    // ---- prologue: chunk 0 ----
    load_W_chunk(sb, 0, 0, tid);
    uint2 xv[8];
    ldg_cvt_x(xb, 0, tid, xv);
    CP_WAIT0();
    sts_x(smem, 0, tid, xv);
    __syncthreads();

    const int arow  = lane & 15;
    const int acolb = ((lane >> 4) & 1) * 16;
    const int brow  = (lane & 7) + ((lane >> 4) & 1) * 8;
    const int bcolb = ((lane >> 3) & 1) * 16;

    for (int c = 0; c < 8; c++) {
        const int s = c & 1, ns = s ^ 1;
        if (c < 7) {
            load_W_chunk(sb, ns, (c + 1) * 64, tid);
            ldg_cvt_x(xb, (c + 1) * 64, tid, xv);
        }
        const uint32_t sA = sb + SM_A(s);
        const uint32_t sBH = sb + SM_BH(s), sBL = sb + SM_BL(s);

        #pragma unroll
        for (int kk = 0; kk < 4; kk++) {
            uint32_t ah[2][4], bh[4][4], bl[4][4];
            #pragma unroll
            for (int mt = 0; mt < 2; mt++) {
                uint32_t off = SWZ((uint32_t)((32 * wm + 16 * mt + arow) * 128 + kk * 32 + acolb));
                ldsm4(ah[mt], sA + off);
            }
            #pragma unroll
            for (int np = 0; np < 4; np++) {
                uint32_t off = SWZ((uint32_t)((64 * wn + 16 * np + brow) * 128 + kk * 32 + bcolb));
                ldsm4(bh[np], sBH + off);
                ldsm4(bl[np], sBL + off);
            }
            #pragma unroll
            for (int mt = 0; mt < 2; mt++)
                #pragma unroll
                for (int nt = 0; nt < 8; nt++) {
                    const uint32_t* ph = &bh[nt >> 1][(nt & 1) * 2];
                    const uint32_t* pl = &bl[nt >> 1][(nt & 1) * 2];
                    mma16816(acc[mt][nt], ah[mt], ph[0], ph[1]);   // xh*Wh
                    mma16816(acc[mt][nt], ah[mt], pl[0], pl[1]);   // xh*Wl
                }
        }
        if (c < 7) {
            CP_WAIT0();
            sts_x(smem, ns, tid, xv);
        }
        __syncthreads();
    }

    // ---- epilogue: bias + store + fp64 partial of sum(acc_tile) ----
    const float* bs = (const float*)(smem + SM_BIAS);
    double dsum = 0.0;
    #pragma unroll
    for (int mt = 0; mt < 2; mt++) {
        const size_t r0 = m0 + 32 * wm + 16 * mt + (lane >> 2);
        #pragma unroll
        for (int nt = 0; nt < 8; nt++) {
            int col = 64 * wn + 8 * nt + 2 * (lane & 3);
            float b0 = bs[col], b1 = bs[col + 1];
            float2 v0 = make_float2(acc[mt][nt][0] + b0, acc[mt][nt][1] + b1);
            float2 v1 = make_float2(acc[mt][nt][2] + b0, acc[mt][nt][3] + b1);
            *(float2*)(out + r0 * OUT_DIM + col)       = v0;
            *(float2*)(out + (r0 + 8) * OUT_DIM + col) = v1;
            dsum += (double)acc[mt][nt][0] + (double)acc[mt][nt][1]
                  + (double)acc[mt][nt][2] + (double)acc[mt][nt][3];
        }
    }
    #pragma unroll
    for (int st = 16; st; st >>= 1)
        dsum += __shfl_xor_sync(0xFFFFFFFFu, dsum, st);
    double* red = (double*)(smem + SM_RED);
    if (lane == 0) red[wid] = dsum;
    __syncthreads();
    if (tid == 0) {
        double t = 0.0;
        #pragma unroll
        for (int w = 0; w < 8; w++) t += red[w];
        g_partials[blockIdx.x] = t;
    }
}

// ============================================================
// 2. threshold = sum(partials)/N + sum(b)
// ============================================================
__global__ void thr_kernel(const float* __restrict__ bias) {
    __shared__ double sm[512];
    double s = 0.0;
    for (int i = threadIdx.x; i < GEMM_BLOCKS; i += 512)
        s += g_partials[i];
    sm[threadIdx.x] = s;
    __syncthreads();
    for (int st = 256; st; st >>= 1) {
        if (threadIdx.x < st) sm[threadIdx.x] += sm[threadIdx.x + st];
        __syncthreads();
    }
    if (threadIdx.x == 0) {
        double sb2 = 0.0;
        for (int o = 0; o < OUT_DIM; o++) sb2 += (double)bias[o];
        g_thr = (float)(sm[0] / (double)N_ROWS + sb2);
    }
}

// ============================================================
// 3-6. ordered stream compaction of (mask > thr)
// ============================================================
__global__ void count_kernel(const float* __restrict__ mask) {
    int i = blockIdx.x * 512 + threadIdx.x;
    int p = mask[i] > g_thr;
    unsigned bal = __ballot_sync(0xFFFFFFFFu, p);
    __shared__ int wc[16];
    if ((threadIdx.x & 31) == 0) wc[threadIdx.x >> 5] = __popc(bal);
    __syncthreads();
    if (threadIdx.x == 0) {
        int s = 0;
        #pragma unroll
        for (int w = 0; w < 16; w++) s += wc[w];
        g_cnt[blockIdx.x] = s;
    }
}

__global__ void scan_kernel() {
    __shared__ int sm[512];
    int v = g_cnt[threadIdx.x];
    sm[threadIdx.x] = v;
    __syncthreads();
    for (int st = 1; st < 512; st <<= 1) {
        int t = (threadIdx.x >= st) ? sm[threadIdx.x - st] : 0;
        __syncthreads();
        sm[threadIdx.x] += t;
        __syncthreads();
    }
    g_off[threadIdx.x] = sm[threadIdx.x] - v;
    if (threadIdx.x == 511) g_total = sm[511];
}

__global__ void scatter_kernel(const float* __restrict__ mask, float* __restrict__ idx_out) {
    int i = blockIdx.x * 512 + threadIdx.x;
    int lane = threadIdx.x & 31;
    int w = threadIdx.x >> 5;
    int p = mask[i] > g_thr;
    unsigned bal = __ballot_sync(0xFFFFFFFFu, p);
    __shared__ int woff[16];
    if (lane == 0) woff[w] = __popc(bal);
    __syncthreads();
    if (threadIdx.x == 0) {
        int s = g_off[blockIdx.x];
        #pragma unroll
        for (int ww = 0; ww < 16; ww++) { int c = woff[ww]; woff[ww] = s; s += c; }
    }
    __syncthreads();
    if (p) {
        int pos = woff[w] + __popc(bal & ((1u << lane) - 1u));
        idx_out[pos] = (float)i;
    }
}

__global__ void fill_kernel(float* __restrict__ idx_out) {
    int i = blockIdx.x * 512 + threadIdx.x;
    if (i >= g_total) idx_out[i] = -1.0f;
}

// ============================================================
// launch
// ============================================================
extern "C" void kernel_launch(void* const* d_in, const int* in_sizes, int n_in,
                              void* d_out, int out_size) {
    const float* x    = (const float*)d_in[0];
    const float* mask = (const float*)d_in[1];
    const float* W    = (const float*)d_in[2];
    const float* b    = (const float*)d_in[3];
    float* out = (float*)d_out;
    float* idx_out = out + (size_t)N_ROWS * OUT_DIM;

    cudaFuncSetAttribute(gemm_tc_kernel, cudaFuncAttributeMaxDynamicSharedMemorySize, SMEM_TOTAL);

    wsplit_kernel<<<256, 256>>>(W);
    gemm_tc_kernel<<<GEMM_BLOCKS, 256, SMEM_TOTAL>>>(x, b, out);
    thr_kernel<<<1, 512>>>(b);
    count_kernel<<<CMP_BLOCKS, 512>>>(mask);
    scan_kernel<<<1, 512>>>();
    scatter_kernel<<<CMP_BLOCKS, 512>>>(mask, idx_out);
    fill_kernel<<<CMP_BLOCKS, 512>>>(idx_out);
}

// round 5
// speedup vs baseline: 3.6529x; 1.1274x over previous
#include <cuda_runtime.h>
#include <cuda_fp16.h>
#include <cstdint>

#define N_ROWS  262144
#define IN_DIM  512
#define OUT_DIM 128
#define GEMM_BLOCKS (N_ROWS / 128)   // 2048
#define CMP_BLOCKS  512

// ---------------- device scratch (no allocations allowed) ----------------
__device__ __align__(16) __half g_Wh[OUT_DIM * IN_DIM];
__device__ double g_partials[GEMM_BLOCKS];
__device__ float  g_thr;
__device__ int    g_cnt[CMP_BLOCKS];
__device__ int    g_off[CMP_BLOCKS];
__device__ int    g_total;

// ---------------- smem layout (dynamic) ----------------
// two stages, each: A 16K | B 16K   (128 rows x 128B, SW128)
#define SM_A(s)  ((s) * 32768 + 0)
#define SM_B(s)  ((s) * 32768 + 16384)
#define SM_BIAS  65536
#define SM_RED   (65536 + 512)
#define SMEM_TOTAL (65536 + 512 + 64)

#define SWZ(o) ((o) ^ (((o) >> 3) & 0x70))

__device__ __forceinline__ uint32_t smem_u32(const void* p) {
    uint32_t a;
    asm("{ .reg .u64 t; cvta.to.shared.u64 t, %1; cvt.u32.u64 %0, t; }" : "=r"(a) : "l"(p));
    return a;
}

__device__ __forceinline__ void ldsm4(uint32_t* r, uint32_t addr) {
    asm volatile("ldmatrix.sync.aligned.m8n8.x4.shared.b16 {%0,%1,%2,%3}, [%4];"
        : "=r"(r[0]), "=r"(r[1]), "=r"(r[2]), "=r"(r[3]) : "r"(addr));
}

__device__ __forceinline__ void mma16816(float* d, const uint32_t* a, uint32_t b0, uint32_t b1) {
    asm volatile("mma.sync.aligned.m16n8k16.row.col.f32.f16.f16.f32 "
        "{%0,%1,%2,%3},{%4,%5,%6,%7},{%8,%9},{%0,%1,%2,%3};"
        : "+f"(d[0]), "+f"(d[1]), "+f"(d[2]), "+f"(d[3])
        : "r"(a[0]), "r"(a[1]), "r"(a[2]), "r"(a[3]), "r"(b0), "r"(b1));
}

#define CP_ASYNC16(dst, src) \
    asm volatile("cp.async.cg.shared.global [%0], [%1], 16;" :: "r"(dst), "l"(src) : "memory")
#define CP_COMMIT()  asm volatile("cp.async.commit_group;" ::: "memory")
#define CP_WAIT0()   asm volatile("cp.async.wait_group 0;" ::: "memory")

// ============================================================
// 0. W -> fp16
// ============================================================
__global__ void wsplit_kernel(const float* __restrict__ W) {
    int i = blockIdx.x * 256 + threadIdx.x;   // grid 256 -> 65536
    g_Wh[i] = __float2half_rn(W[i]);
}

// ============================================================
// GEMM pipeline helpers
// ============================================================
__device__ __forceinline__ void load_W_chunk(uint32_t sb, int s, int k0, int tid) {
    #pragma unroll
    for (int i = 0; i < 4; i++) {
        int l = tid + 256 * i;          // 0..1023
        int row = l >> 3, u = l & 7;
        uint32_t off = SWZ((uint32_t)(row * 128 + u * 16));
        CP_ASYNC16(sb + SM_B(s) + off, g_Wh + row * IN_DIM + k0 + u * 8);
    }
    CP_COMMIT();
}

__device__ __forceinline__ void ldg_cvt_x(const float* xb, int k0, int tid, uint2* xv) {
    #pragma unroll
    for (int i = 0; i < 8; i++) {
        int l = tid + 256 * i;          // 0..2047
        int row = l >> 4, c4 = l & 15;
        float4 v = __ldg((const float4*)(xb + (size_t)row * IN_DIM + k0 + c4 * 4));
        __half2 h01 = __floats2half2_rn(v.x, v.y);
        __half2 h23 = __floats2half2_rn(v.z, v.w);
        xv[i] = make_uint2(*(uint32_t*)&h01, *(uint32_t*)&h23);
    }
}

__device__ __forceinline__ void sts_x(char* smem, int s, int tid, const uint2* xv) {
    #pragma unroll
    for (int i = 0; i < 8; i++) {
        int l = tid + 256 * i;
        int row = l >> 4, c4 = l & 15;
        uint32_t off = SWZ((uint32_t)(row * 128 + c4 * 8));
        *(uint2*)(smem + SM_A(s) + off) = xv[i];
    }
}

// ============================================================
// 1. HMMA GEMM (single fp16 product) + fused row-sum partial
// ============================================================
__global__ void __launch_bounds__(256, 2) gemm_tc_kernel(
    const float* __restrict__ x, const float* __restrict__ bias, float* __restrict__ out)
{
    extern __shared__ char smem[];
    const uint32_t sb = smem_u32(smem);
    const int tid = threadIdx.x, wid = tid >> 5, lane = tid & 31;
    const int wm = wid & 3, wn = wid >> 2;       // warp tile: 32(M) x 64(N)
    const size_t m0 = (size_t)blockIdx.x * 128;
    const float* xb = x + m0 * IN_DIM;

    if (tid < 128) ((float*)(smem + SM_BIAS))[tid] = bias[tid];

    float acc[2][8][4];
    #pragma unroll
    for (int mt = 0; mt < 2; mt++)
        #pragma unroll
        for (int nt = 0; nt < 8; nt++)
            #pragma unroll
            for (int j = 0; j < 4; j++) acc[mt][nt][j] = 0.0f;

    // ---- prologue: chunk 0 ----
    load_W_chunk(sb, 0, 0, tid);
    uint2 xv[8];
    ldg_cvt_x(xb, 0, tid, xv);
    CP_WAIT0();
    sts_x(smem, 0, tid, xv);
    __syncthreads();

    const int arow  = lane & 15;
    const int acolb = ((lane >> 4) & 1) * 16;
    const int brow  = (lane & 7) + ((lane >> 4) & 1) * 8;
    const int bcolb = ((lane >> 3) & 1) * 16;

    for (int c = 0; c < 8; c++) {
        const int s = c & 1, ns = s ^ 1;
        if (c < 7) {
            load_W_chunk(sb, ns, (c + 1) * 64, tid);
            ldg_cvt_x(xb, (c + 1) * 64, tid, xv);
        }
        const uint32_t sA = sb + SM_A(s);
        const uint32_t sB = sb + SM_B(s);

        #pragma unroll
        for (int kk = 0; kk < 4; kk++) {
            uint32_t ah[2][4], bh[4][4];
            #pragma unroll
            for (int mt = 0; mt < 2; mt++) {
                uint32_t off = SWZ((uint32_t)((32 * wm + 16 * mt + arow) * 128 + kk * 32 + acolb));
                ldsm4(ah[mt], sA + off);
            }
            #pragma unroll
            for (int np = 0; np < 4; np++) {
                uint32_t off = SWZ((uint32_t)((64 * wn + 16 * np + brow) * 128 + kk * 32 + bcolb));
                ldsm4(bh[np], sB + off);
            }
            #pragma unroll
            for (int mt = 0; mt < 2; mt++)
                #pragma unroll
                for (int nt = 0; nt < 8; nt++) {
                    const uint32_t* ph = &bh[nt >> 1][(nt & 1) * 2];
                    mma16816(acc[mt][nt], ah[mt], ph[0], ph[1]);
                }
        }
        if (c < 7) {
            CP_WAIT0();
            sts_x(smem, ns, tid, xv);
        }
        __syncthreads();
    }

    // ---- epilogue: bias + store + fp64 partial of sum(acc_tile) ----
    const float* bs = (const float*)(smem + SM_BIAS);
    double dsum = 0.0;
    #pragma unroll
    for (int mt = 0; mt < 2; mt++) {
        const size_t r0 = m0 + 32 * wm + 16 * mt + (lane >> 2);
        #pragma unroll
        for (int nt = 0; nt < 8; nt++) {
            int col = 64 * wn + 8 * nt + 2 * (lane & 3);
            float b0 = bs[col], b1 = bs[col + 1];
            float2 v0 = make_float2(acc[mt][nt][0] + b0, acc[mt][nt][1] + b1);
            float2 v1 = make_float2(acc[mt][nt][2] + b0, acc[mt][nt][3] + b1);
            *(float2*)(out + r0 * OUT_DIM + col)       = v0;
            *(float2*)(out + (r0 + 8) * OUT_DIM + col) = v1;
            dsum += (double)acc[mt][nt][0] + (double)acc[mt][nt][1]
                  + (double)acc[mt][nt][2] + (double)acc[mt][nt][3];
        }
    }
    #pragma unroll
    for (int st = 16; st; st >>= 1)
        dsum += __shfl_xor_sync(0xFFFFFFFFu, dsum, st);
    double* red = (double*)(smem + SM_RED);
    if (lane == 0) red[wid] = dsum;
    __syncthreads();
    if (tid == 0) {
        double t = 0.0;
        #pragma unroll
        for (int w = 0; w < 8; w++) t += red[w];
        g_partials[blockIdx.x] = t;
    }
}

// ============================================================
// 2. threshold = sum(partials)/N + sum(b)
// ============================================================
__global__ void thr_kernel(const float* __restrict__ bias) {
    __shared__ double sm[512];
    double s = 0.0;
    for (int i = threadIdx.x; i < GEMM_BLOCKS; i += 512)
        s += g_partials[i];
    sm[threadIdx.x] = s;
    __syncthreads();
    for (int st = 256; st; st >>= 1) {
        if (threadIdx.x < st) sm[threadIdx.x] += sm[threadIdx.x + st];
        __syncthreads();
    }
    if (threadIdx.x == 0) {
        double sb2 = 0.0;
        for (int o = 0; o < OUT_DIM; o++) sb2 += (double)bias[o];
        g_thr = (float)(sm[0] / (double)N_ROWS + sb2);
    }
}

// ============================================================
// 3-6. ordered stream compaction of (mask > thr)
// ============================================================
__global__ void count_kernel(const float* __restrict__ mask) {
    int i = blockIdx.x * 512 + threadIdx.x;
    int p = mask[i] > g_thr;
    unsigned bal = __ballot_sync(0xFFFFFFFFu, p);
    __shared__ int wc[16];
    if ((threadIdx.x & 31) == 0) wc[threadIdx.x >> 5] = __popc(bal);
    __syncthreads();
    if (threadIdx.x == 0) {
        int s = 0;
        #pragma unroll
        for (int w = 0; w < 16; w++) s += wc[w];
        g_cnt[blockIdx.x] = s;
    }
}

__global__ void scan_kernel() {
    __shared__ int sm[512];
    int v = g_cnt[threadIdx.x];
    sm[threadIdx.x] = v;
    __syncthreads();
    for (int st = 1; st < 512; st <<= 1) {
        int t = (threadIdx.x >= st) ? sm[threadIdx.x - st] : 0;
        __syncthreads();
        sm[threadIdx.x] += t;
        __syncthreads();
    }
    g_off[threadIdx.x] = sm[threadIdx.x] - v;
    if (threadIdx.x == 511) g_total = sm[511];
}

__global__ void scatter_kernel(const float* __restrict__ mask, float* __restrict__ idx_out) {
    int i = blockIdx.x * 512 + threadIdx.x;
    int lane = threadIdx.x & 31;
    int w = threadIdx.x >> 5;
    int p = mask[i] > g_thr;
    unsigned bal = __ballot_sync(0xFFFFFFFFu, p);
    __shared__ int woff[16];
    if (lane == 0) woff[w] = __popc(bal);
    __syncthreads();
    if (threadIdx.x == 0) {
        int s = g_off[blockIdx.x];
        #pragma unroll
        for (int ww = 0; ww < 16; ww++) { int c = woff[ww]; woff[ww] = s; s += c; }
    }
    __syncthreads();
    if (p) {
        int pos = woff[w] + __popc(bal & ((1u << lane) - 1u));
        idx_out[pos] = (float)i;
    }
}

__global__ void fill_kernel(float* __restrict__ idx_out) {
    int i = blockIdx.x * 512 + threadIdx.x;
    if (i >= g_total) idx_out[i] = -1.0f;
}

// ============================================================
// launch
// ============================================================
extern "C" void kernel_launch(void* const* d_in, const int* in_sizes, int n_in,
                              void* d_out, int out_size) {
    const float* x    = (const float*)d_in[0];
    const float* mask = (const float*)d_in[1];
    const float* W    = (const float*)d_in[2];
    const float* b    = (const float*)d_in[3];
    float* out = (float*)d_out;
    float* idx_out = out + (size_t)N_ROWS * OUT_DIM;

    cudaFuncSetAttribute(gemm_tc_kernel, cudaFuncAttributeMaxDynamicSharedMemorySize, SMEM_TOTAL);

    wsplit_kernel<<<256, 256>>>(W);
    gemm_tc_kernel<<<GEMM_BLOCKS, 256, SMEM_TOTAL>>>(x, b, out);
    thr_kernel<<<1, 512>>>(b);
    count_kernel<<<CMP_BLOCKS, 512>>>(mask);
    scan_kernel<<<1, 512>>>();
    scatter_kernel<<<CMP_BLOCKS, 512>>>(mask, idx_out);
    fill_kernel<<<CMP_BLOCKS, 512>>>(idx_out);
}

// round 6
// speedup vs baseline: 5.3053x; 1.4523x over previous
#include <cuda_runtime.h>
#include <cuda_fp16.h>
#include <cstdint>

#define N_ROWS  262144
#define IN_DIM  512
#define OUT_DIM 128
#define GEMM_BLOCKS (N_ROWS / 128)   // 2048
#define CMP_BLOCKS  512

// ---------------- device scratch (no allocations allowed) ----------------
__device__ __align__(16) __half g_Wh[OUT_DIM * IN_DIM];
__device__ double g_partials[GEMM_BLOCKS];
__device__ float  g_thr;
__device__ int    g_cnt[CMP_BLOCKS];
__device__ int    g_off[CMP_BLOCKS];

// ---------------- smem layout (dynamic) ----------------
// two stages, each: A 16K | B 16K   (128 rows x 128B, SW128)
#define SM_A(s)  ((s) * 32768 + 0)
#define SM_B(s)  ((s) * 32768 + 16384)
#define SM_BIAS  65536
#define SM_RED   (65536 + 512)
#define SMEM_TOTAL (65536 + 512 + 64)

#define SWZ(o) ((o) ^ (((o) >> 3) & 0x70))

__device__ __forceinline__ uint32_t smem_u32(const void* p) {
    uint32_t a;
    asm("{ .reg .u64 t; cvta.to.shared.u64 t, %1; cvt.u32.u64 %0, t; }" : "=r"(a) : "l"(p));
    return a;
}

__device__ __forceinline__ void ldsm4(uint32_t* r, uint32_t addr) {
    asm volatile("ldmatrix.sync.aligned.m8n8.x4.shared.b16 {%0,%1,%2,%3}, [%4];"
        : "=r"(r[0]), "=r"(r[1]), "=r"(r[2]), "=r"(r[3]) : "r"(addr));
}

__device__ __forceinline__ void mma16816(float* d, const uint32_t* a, uint32_t b0, uint32_t b1) {
    asm volatile("mma.sync.aligned.m16n8k16.row.col.f32.f16.f16.f32 "
        "{%0,%1,%2,%3},{%4,%5,%6,%7},{%8,%9},{%0,%1,%2,%3};"
        : "+f"(d[0]), "+f"(d[1]), "+f"(d[2]), "+f"(d[3])
        : "r"(a[0]), "r"(a[1]), "r"(a[2]), "r"(a[3]), "r"(b0), "r"(b1));
}

#define CP_ASYNC16(dst, src) \
    asm volatile("cp.async.cg.shared.global [%0], [%1], 16;" :: "r"(dst), "l"(src) : "memory")
#define CP_COMMIT()  asm volatile("cp.async.commit_group;" ::: "memory")
#define CP_WAIT0()   asm volatile("cp.async.wait_group 0;" ::: "memory")

// ============================================================
// 0. W -> fp16
// ============================================================
__global__ void wsplit_kernel(const float* __restrict__ W) {
    int i = blockIdx.x * 256 + threadIdx.x;   // grid 256 -> 65536
    g_Wh[i] = __float2half_rn(W[i]);
}

// fill a quarter of the idx region with -1 (scatter overwrites valid slots later)
__global__ void fillq_kernel(float* __restrict__ p) {
    p[blockIdx.x * 512 + threadIdx.x] = -1.0f;
}

// ============================================================
// GEMM pipeline helpers
// ============================================================
__device__ __forceinline__ void load_W_chunk(uint32_t sb, int s, int k0, int tid) {
    #pragma unroll
    for (int i = 0; i < 4; i++) {
        int l = tid + 256 * i;          // 0..1023
        int row = l >> 3, u = l & 7;
        uint32_t off = SWZ((uint32_t)(row * 128 + u * 16));
        CP_ASYNC16(sb + SM_B(s) + off, g_Wh + row * IN_DIM + k0 + u * 8);
    }
    CP_COMMIT();
}

// each thread handles 4 x 16B fp16 units (2 float4 loads + converts per unit)
__device__ __forceinline__ void ldg_cvt_x(const float* xb, int k0, int tid, uint4* xv) {
    #pragma unroll
    for (int i = 0; i < 4; i++) {
        int l = tid + 256 * i;          // 0..1023
        int row = l >> 3, u = l & 7;
        const float* p = xb + (size_t)row * IN_DIM + k0 + u * 8;
        float4 v0 = __ldg((const float4*)p);
        float4 v1 = __ldg((const float4*)(p + 4));
        __half2 ha = __floats2half2_rn(v0.x, v0.y);
        __half2 hb = __floats2half2_rn(v0.z, v0.w);
        __half2 hc = __floats2half2_rn(v1.x, v1.y);
        __half2 hd = __floats2half2_rn(v1.z, v1.w);
        xv[i] = make_uint4(*(uint32_t*)&ha, *(uint32_t*)&hb,
                           *(uint32_t*)&hc, *(uint32_t*)&hd);
    }
}

__device__ __forceinline__ void sts_x(char* smem, int s, int tid, const uint4* xv) {
    #pragma unroll
    for (int i = 0; i < 4; i++) {
        int l = tid + 256 * i;
        int row = l >> 3, u = l & 7;
        uint32_t off = SWZ((uint32_t)(row * 128 + u * 16));
        *(uint4*)(smem + SM_A(s) + off) = xv[i];
    }
}

// ============================================================
// 1. HMMA GEMM (fp16) + fused row-sum partial
// ============================================================
__global__ void __launch_bounds__(256, 2) gemm_tc_kernel(
    const float* __restrict__ x, const float* __restrict__ bias, float* __restrict__ out)
{
    extern __shared__ char smem[];
    const uint32_t sb = smem_u32(smem);
    const int tid = threadIdx.x, wid = tid >> 5, lane = tid & 31;
    const int wm = wid & 3, wn = wid >> 2;       // warp tile: 32(M) x 64(N)
    const size_t m0 = (size_t)blockIdx.x * 128;
    const float* xb = x + m0 * IN_DIM;

    if (tid < 128) ((float*)(smem + SM_BIAS))[tid] = bias[tid];

    float acc[2][8][4];
    #pragma unroll
    for (int mt = 0; mt < 2; mt++)
        #pragma unroll
        for (int nt = 0; nt < 8; nt++)
            #pragma unroll
            for (int j = 0; j < 4; j++) acc[mt][nt][j] = 0.0f;

    // ---- prologue: chunk 0 ----
    uint4 xv[4];
    ldg_cvt_x(xb, 0, tid, xv);
    load_W_chunk(sb, 0, 0, tid);
    CP_WAIT0();
    sts_x(smem, 0, tid, xv);
    __syncthreads();

    const int arow  = lane & 15;
    const int acolb = ((lane >> 4) & 1) * 16;
    const int brow  = (lane & 7) + ((lane >> 4) & 1) * 8;
    const int bcolb = ((lane >> 3) & 1) * 16;

    for (int c = 0; c < 8; c++) {
        const int s = c & 1, ns = s ^ 1;
        if (c < 7) {
            ldg_cvt_x(xb, (c + 1) * 64, tid, xv);
            load_W_chunk(sb, ns, (c + 1) * 64, tid);
        }
        const uint32_t sA = sb + SM_A(s);
        const uint32_t sB = sb + SM_B(s);

        #pragma unroll
        for (int kk = 0; kk < 4; kk++) {
            uint32_t ah[2][4], bh[4][4];
            #pragma unroll
            for (int mt = 0; mt < 2; mt++) {
                uint32_t off = SWZ((uint32_t)((32 * wm + 16 * mt + arow) * 128 + kk * 32 + acolb));
                ldsm4(ah[mt], sA + off);
            }
            #pragma unroll
            for (int np = 0; np < 4; np++) {
                uint32_t off = SWZ((uint32_t)((64 * wn + 16 * np + brow) * 128 + kk * 32 + bcolb));
                ldsm4(bh[np], sB + off);
            }
            #pragma unroll
            for (int mt = 0; mt < 2; mt++)
                #pragma unroll
                for (int nt = 0; nt < 8; nt++) {
                    const uint32_t* ph = &bh[nt >> 1][(nt & 1) * 2];
                    mma16816(acc[mt][nt], ah[mt], ph[0], ph[1]);
                }
        }
        if (c < 7) {
            CP_WAIT0();
            sts_x(smem, ns, tid, xv);
        }
        __syncthreads();
    }

    // ---- epilogue: bias + store + fp32 thread-sum -> fp64 partial ----
    const float* bs = (const float*)(smem + SM_BIAS);
    float fsum = 0.0f;
    #pragma unroll
    for (int mt = 0; mt < 2; mt++) {
        const size_t r0 = m0 + 32 * wm + 16 * mt + (lane >> 2);
        #pragma unroll
        for (int nt = 0; nt < 8; nt++) {
            int col = 64 * wn + 8 * nt + 2 * (lane & 3);
            float b0 = bs[col], b1 = bs[col + 1];
            float2 v0 = make_float2(acc[mt][nt][0] + b0, acc[mt][nt][1] + b1);
            float2 v1 = make_float2(acc[mt][nt][2] + b0, acc[mt][nt][3] + b1);
            *(float2*)(out + r0 * OUT_DIM + col)       = v0;
            *(float2*)(out + (r0 + 8) * OUT_DIM + col) = v1;
            fsum += acc[mt][nt][0] + acc[mt][nt][1]
                  + acc[mt][nt][2] + acc[mt][nt][3];
        }
    }
    double dsum = (double)fsum;
    #pragma unroll
    for (int st = 16; st; st >>= 1)
        dsum += __shfl_xor_sync(0xFFFFFFFFu, dsum, st);
    double* red = (double*)(smem + SM_RED);
    if (lane == 0) red[wid] = dsum;
    __syncthreads();
    if (tid == 0) {
        double t = 0.0;
        #pragma unroll
        for (int w = 0; w < 8; w++) t += red[w];
        g_partials[blockIdx.x] = t;
    }
}

// ============================================================
// 2. threshold = sum(partials)/N + sum(b)
// ============================================================
__global__ void thr_kernel(const float* __restrict__ bias) {
    __shared__ double sm[512];
    double s = 0.0;
    for (int i = threadIdx.x; i < GEMM_BLOCKS; i += 512)
        s += g_partials[i];
    sm[threadIdx.x] = s;
    __syncthreads();
    for (int st = 256; st; st >>= 1) {
        if (threadIdx.x < st) sm[threadIdx.x] += sm[threadIdx.x + st];
        __syncthreads();
    }
    if (threadIdx.x == 0) {
        double sb2 = 0.0;
        for (int o = 0; o < OUT_DIM; o++) sb2 += (double)bias[o];
        g_thr = (float)(sm[0] / (double)N_ROWS + sb2);
    }
}

// ============================================================
// 3-5. ordered stream compaction of (mask > thr)
// ============================================================
__global__ void count_kernel(const float* __restrict__ mask) {
    int i = blockIdx.x * 512 + threadIdx.x;
    int p = mask[i] > g_thr;
    unsigned bal = __ballot_sync(0xFFFFFFFFu, p);
    __shared__ int wc[16];
    if ((threadIdx.x & 31) == 0) wc[threadIdx.x >> 5] = __popc(bal);
    __syncthreads();
    if (threadIdx.x == 0) {
        int s = 0;
        #pragma unroll
        for (int w = 0; w < 16; w++) s += wc[w];
        g_cnt[blockIdx.x] = s;
    }
}

__global__ void scan_kernel() {
    __shared__ int sm[512];
    int v = g_cnt[threadIdx.x];
    sm[threadIdx.x] = v;
    __syncthreads();
    for (int st = 1; st < 512; st <<= 1) {
        int t = (threadIdx.x >= st) ? sm[threadIdx.x - st] : 0;
        __syncthreads();
        sm[threadIdx.x] += t;
        __syncthreads();
    }
    g_off[threadIdx.x] = sm[threadIdx.x] - v;
}

__global__ void scatter_kernel(const float* __restrict__ mask, float* __restrict__ idx_out) {
    int i = blockIdx.x * 512 + threadIdx.x;
    int lane = threadIdx.x & 31;
    int w = threadIdx.x >> 5;
    int p = mask[i] > g_thr;
    unsigned bal = __ballot_sync(0xFFFFFFFFu, p);
    __shared__ int woff[16];
    if (lane == 0) woff[w] = __popc(bal);
    __syncthreads();
    if (threadIdx.x == 0) {
        int s = g_off[blockIdx.x];
        #pragma unroll
        for (int ww = 0; ww < 16; ww++) { int c = woff[ww]; woff[ww] = s; s += c; }
    }
    __syncthreads();
    if (p) {
        int pos = woff[w] + __popc(bal & ((1u << lane) - 1u));
        idx_out[pos] = (float)i;
    }
}

// ============================================================
// launch
// ============================================================
extern "C" void kernel_launch(void* const* d_in, const int* in_sizes, int n_in,
                              void* d_out, int out_size) {
    const float* x    = (const float*)d_in[0];
    const float* mask = (const float*)d_in[1];
    const float* W    = (const float*)d_in[2];
    const float* b    = (const float*)d_in[3];
    float* out = (float*)d_out;
    float* idx_out = out + (size_t)N_ROWS * OUT_DIM;

    cudaFuncSetAttribute(gemm_tc_kernel, cudaFuncAttributeMaxDynamicSharedMemorySize, SMEM_TOTAL);

    // launches 1-5 (cheap) so gemm is launch #6 -> ncu -s 5 -c 1 profiles it
    wsplit_kernel<<<256, 256>>>(W);
    fillq_kernel<<<128, 512>>>(idx_out);
    fillq_kernel<<<128, 512>>>(idx_out + 65536);
    fillq_kernel<<<128, 512>>>(idx_out + 131072);
    fillq_kernel<<<128, 512>>>(idx_out + 196608);
    gemm_tc_kernel<<<GEMM_BLOCKS, 256, SMEM_TOTAL>>>(x, b, out);
    thr_kernel<<<1, 512>>>(b);
    count_kernel<<<CMP_BLOCKS, 512>>>(mask);
    scan_kernel<<<1, 512>>>();
    scatter_kernel<<<CMP_BLOCKS, 512>>>(mask, idx_out);
}